// round 16
// baseline (speedup 1.0000x reference)
#include <cuda_runtime.h>
#include <cstdint>
#include <cstddef>

// ---------------------------------------------------------------------------
// NSHE fused: per-type encoder GEMM (relu(feat@W+b)) FUSED with GCN linear
// (@gcn_W + gcn_b) in one kernel -> g_support. Then edge gather*w scatter-add
// (L2 vector atomics) -> row L2-normalize.
// GEMM stage-1: tf32 mma.sync m16n8k8, 3-stage cp.async pipeline, BM=128,
// 128 threads (4 warps x 32x64 warp tile), one __syncthreads per k-iter.
// GEMM stage-2: block-local 128x64 @ 64x64 from smem (gcn_W tf32 in smem).
// ---------------------------------------------------------------------------

#define NMAX 200000

__device__ float g_support[(size_t)NMAX * 64];

// ---- helpers --------------------------------------------------------------
__device__ __forceinline__ unsigned tf32u(float x) {
    unsigned u;
    asm("cvt.rna.tf32.f32 %0, %1;" : "=r"(u) : "f"(x));
    return u;
}
__device__ __forceinline__ float tf32f(float x) {
    return __uint_as_float(tf32u(x));
}

__device__ __forceinline__ void mma_tf32(float* c, const unsigned* a,
                                         const unsigned* b) {
    asm volatile(
        "mma.sync.aligned.m16n8k8.row.col.f32.tf32.tf32.f32 "
        "{%0,%1,%2,%3}, {%4,%5,%6,%7}, {%8,%9}, {%0,%1,%2,%3};"
        : "+f"(c[0]), "+f"(c[1]), "+f"(c[2]), "+f"(c[3])
        : "r"(a[0]), "r"(a[1]), "r"(a[2]), "r"(a[3]), "r"(b[0]), "r"(b[1]));
}

__device__ __forceinline__ void cp16(uint32_t dst, const void* src, bool p) {
    int sz = p ? 16 : 0;
    asm volatile("cp.async.cg.shared.global [%0], [%1], 16, %2;"
                 :: "r"(dst), "l"(src), "r"(sz));
}

// ---------------------------------------------------------------------------
// Dynamic smem layout (floats), total 20736 floats = 82944 B:
//   stage 1: sA[3][128][36]  (3*4608 = 13824)   raw fp32 via cp.async
//            sB[3][32][72]   (3*2304 =  6912)   at offset 13824
//   stage 2 (aliased): sE[128][68] (8704, fits in sA region)
//                      sW2[64][72] (4608, at offset 13824)
// ---------------------------------------------------------------------------
template <int K>
__global__ void __launch_bounds__(128, 2)
fused_enc_gcn(const float* __restrict__ A, const float* __restrict__ W1,
              const float* __restrict__ b1, const float* __restrict__ gW,
              const float* __restrict__ gb, float* __restrict__ out, int nRows)
{
    extern __shared__ float smem[];
    float* sA = smem;              // 3 buffers, stride 4608 floats
    float* sB = smem + 13824;      // 3 buffers, stride 2304 floats

    const int t    = threadIdx.x;          // 0..127
    const int warp = t >> 5;                // 0..3
    const int lane = t & 31;
    const int row0 = blockIdx.x * 128;
    const int wrow = warp * 32;
    const int g4   = lane >> 2;             // 0..7
    const int t4   = lane & 3;              // 0..3

    const uint32_t sA_u = (uint32_t)__cvta_generic_to_shared(sA);
    const uint32_t sB_u = sA_u + 13824u * 4u;

    float acc[2][8][4];
#pragma unroll
    for (int mt = 0; mt < 2; mt++)
#pragma unroll
        for (int nt = 0; nt < 8; nt++)
#pragma unroll
            for (int i = 0; i < 4; i++) acc[mt][nt][i] = 0.f;

    auto load_tiles = [&](int buf, int k0) {
        // A tile: 128 rows x 32 k = 1024 float4, 8 per thread
#pragma unroll
        for (int i = 0; i < 8; i++) {
            int idx = t + i * 128;
            int r   = idx >> 3;        // 0..127
            int f   = idx & 7;         // 0..7
            int gr  = row0 + r;
            bool ok = gr < nRows;
            const float* src = A + (size_t)(ok ? gr : 0) * K + k0 + f * 4;
            cp16(sA_u + (uint32_t)(buf * 4608 + r * 36 + f * 4) * 4, src, ok);
        }
        // B tile: 32 x 64 = 512 float4, 4 per thread
#pragma unroll
        for (int i = 0; i < 4; i++) {
            int idx = t + i * 128;
            int kk  = idx >> 4;        // 0..31
            int f   = idx & 15;        // 0..15
            cp16(sB_u + (uint32_t)(buf * 2304 + kk * 72 + f * 4) * 4,
                 W1 + (size_t)(k0 + kk) * 64 + f * 4, true);
        }
        asm volatile("cp.async.commit_group;");
    };

    constexpr int NIT = K / 32;
    load_tiles(0, 0);
    load_tiles(1, 32);

    for (int it = 0; it < NIT; ++it) {
        if (it + 1 < NIT)
            asm volatile("cp.async.wait_group 1;");
        else
            asm volatile("cp.async.wait_group 0;");
        __syncthreads();
        if (it + 2 < NIT) load_tiles((it + 2) % 3, (it + 2) * 32);

        const float* bA = sA + (it % 3) * 4608;
        const float* bB = sB + (it % 3) * 2304;
#pragma unroll
        for (int k8 = 0; k8 < 4; k8++) {
            unsigned bf[8][2];
#pragma unroll
            for (int nt = 0; nt < 8; nt++) {
                bf[nt][0] = tf32u(bB[(k8 * 8 + t4    ) * 72 + nt * 8 + g4]);
                bf[nt][1] = tf32u(bB[(k8 * 8 + t4 + 4) * 72 + nt * 8 + g4]);
            }
#pragma unroll
            for (int mt = 0; mt < 2; mt++) {
                int r = wrow + mt * 16 + g4;
                unsigned af[4];
                af[0] = tf32u(bA[(r    ) * 36 + k8 * 8 + t4    ]);
                af[1] = tf32u(bA[(r + 8) * 36 + k8 * 8 + t4    ]);
                af[2] = tf32u(bA[(r    ) * 36 + k8 * 8 + t4 + 4]);
                af[3] = tf32u(bA[(r + 8) * 36 + k8 * 8 + t4 + 4]);
#pragma unroll
                for (int nt = 0; nt < 8; nt++)
                    mma_tf32(acc[mt][nt], af, bf[nt]);
            }
        }
        // no trailing sync: next iter's sync (after wait) protects buffers
    }
    __syncthreads();   // all compute done before smem is re-purposed

    // ---- stage 2 setup: relu(acc+b1) -> sE (tf32), gcn_W -> sW2 (tf32) ----
    float* sE  = smem;           // [128][68]
    float* sW2 = smem + 13824;   // [64][72]

#pragma unroll
    for (int nt = 0; nt < 8; nt++) {
        int col   = nt * 8 + 2 * t4;
        float bb0 = b1[col];
        float bb1 = b1[col + 1];
#pragma unroll
        for (int mt = 0; mt < 2; mt++)
#pragma unroll
            for (int h = 0; h < 2; h++) {
                int r = wrow + mt * 16 + h * 8 + g4;
                float x0 = fmaxf(acc[mt][nt][h * 2 + 0] + bb0, 0.f);
                float x1 = fmaxf(acc[mt][nt][h * 2 + 1] + bb1, 0.f);
                *reinterpret_cast<float2*>(&sE[r * 68 + col]) =
                    make_float2(tf32f(x0), tf32f(x1));
            }
    }
#pragma unroll
    for (int i = 0; i < 8; i++) {
        int idx = t + i * 128;   // 0..1023
        int kk  = idx >> 4;
        int f   = idx & 15;
        float4 v = *reinterpret_cast<const float4*>(gW + (size_t)kk * 64 + f * 4);
        sW2[kk * 72 + f * 4 + 0] = tf32f(v.x);
        sW2[kk * 72 + f * 4 + 1] = tf32f(v.y);
        sW2[kk * 72 + f * 4 + 2] = tf32f(v.z);
        sW2[kk * 72 + f * 4 + 3] = tf32f(v.w);
    }
    __syncthreads();

    // ---- stage 2 MMA: 128x64 @ 64x64 (reuse acc registers) ----
#pragma unroll
    for (int mt = 0; mt < 2; mt++)
#pragma unroll
        for (int nt = 0; nt < 8; nt++)
#pragma unroll
            for (int i = 0; i < 4; i++) acc[mt][nt][i] = 0.f;

#pragma unroll
    for (int k8 = 0; k8 < 8; k8++) {
        unsigned bf[8][2];
#pragma unroll
        for (int nt = 0; nt < 8; nt++) {
            bf[nt][0] = __float_as_uint(sW2[(k8 * 8 + t4    ) * 72 + nt * 8 + g4]);
            bf[nt][1] = __float_as_uint(sW2[(k8 * 8 + t4 + 4) * 72 + nt * 8 + g4]);
        }
#pragma unroll
        for (int mt = 0; mt < 2; mt++) {
            int r = wrow + mt * 16 + g4;
            unsigned af[4];
            af[0] = __float_as_uint(sE[(r    ) * 68 + k8 * 8 + t4    ]);
            af[1] = __float_as_uint(sE[(r + 8) * 68 + k8 * 8 + t4    ]);
            af[2] = __float_as_uint(sE[(r    ) * 68 + k8 * 8 + t4 + 4]);
            af[3] = __float_as_uint(sE[(r + 8) * 68 + k8 * 8 + t4 + 4]);
#pragma unroll
            for (int nt = 0; nt < 8; nt++)
                mma_tf32(acc[mt][nt], af, bf[nt]);
        }
    }

    // ---- epilogue: + gcn_b, store support ----
#pragma unroll
    for (int nt = 0; nt < 8; nt++) {
        int col   = nt * 8 + 2 * t4;
        float bb0 = gb[col];
        float bb1 = gb[col + 1];
#pragma unroll
        for (int mt = 0; mt < 2; mt++)
#pragma unroll
            for (int h = 0; h < 2; h++) {
                int gr = row0 + wrow + mt * 16 + h * 8 + g4;
                if (gr < nRows) {
                    *reinterpret_cast<float2*>(out + (size_t)gr * 64 + col) =
                        make_float2(acc[mt][nt][h * 2 + 0] + bb0,
                                    acc[mt][nt][h * 2 + 1] + bb1);
                }
            }
    }
}

// ---------------------------------------------------------------------------
// Edge scatter: out[dst] += support[src] * w, 16 threads/edge (float4 each).
// support (51 MB) + out (51 MB) are L2-resident; v4 red cuts atomic op count.
// ---------------------------------------------------------------------------
__global__ void __launch_bounds__(256)
edge_kernel(const float* __restrict__ support, const int* __restrict__ src,
            const int* __restrict__ dst, const float* __restrict__ w,
            float* __restrict__ out, int E)
{
    int g   = blockIdx.x * 256 + threadIdx.x;
    int e   = g >> 4;
    int sub = g & 15;
    if (e >= E) return;
    int   s  = src[e];
    int   d  = dst[e];
    float wt = w[e];
    float4 v = *reinterpret_cast<const float4*>(support + (size_t)s * 64 + sub * 4);
    float* o = out + (size_t)d * 64 + sub * 4;
    asm volatile("red.global.add.v4.f32 [%0], {%1, %2, %3, %4};"
                 :: "l"(o), "f"(v.x * wt), "f"(v.y * wt),
                    "f"(v.z * wt), "f"(v.w * wt)
                 : "memory");
}

// ---------------------------------------------------------------------------
__global__ void __launch_bounds__(256)
zero_kernel(float4* __restrict__ out, int n4)
{
    int i = blockIdx.x * 256 + threadIdx.x;
    if (i < n4) out[i] = make_float4(0.f, 0.f, 0.f, 0.f);
}

__global__ void __launch_bounds__(256)
normalize_kernel(float* __restrict__ out, int N)
{
    int row  = blockIdx.x * 8 + (threadIdx.x >> 5);
    int lane = threadIdx.x & 31;
    if (row >= N) return;
    float* p = out + (size_t)row * 64;
    float2 v = *reinterpret_cast<float2*>(p + lane * 2);
    float ss = v.x * v.x + v.y * v.y;
#pragma unroll
    for (int o = 16; o > 0; o >>= 1) ss += __shfl_xor_sync(0xFFFFFFFFu, ss, o);
    float inv = 1.0f / fmaxf(sqrtf(ss), 1e-12f);
    v.x *= inv;
    v.y *= inv;
    *reinterpret_cast<float2*>(p + lane * 2) = v;
}

// ---------------------------------------------------------------------------
extern "C" void kernel_launch(void* const* d_in, const int* in_sizes, int n_in,
                              void* d_out, int out_size)
{
    const float* feat_a   = (const float*)d_in[0];
    const float* W_a      = (const float*)d_in[1];
    const float* b_a      = (const float*)d_in[2];
    const float* feat_b   = (const float*)d_in[3];
    const float* W_b      = (const float*)d_in[4];
    const float* b_b      = (const float*)d_in[5];
    const float* feat_c   = (const float*)d_in[6];
    const float* W_c      = (const float*)d_in[7];
    const float* b_c      = (const float*)d_in[8];
    const float* gcn_W    = (const float*)d_in[9];
    const float* gcn_b    = (const float*)d_in[10];
    const float* edge_w   = (const float*)d_in[11];
    const int*   edge_src = (const int*)d_in[12];
    const int*   edge_dst = (const int*)d_in[13];

    const int nA = in_sizes[0] / 512;
    const int nB = in_sizes[3] / 256;
    const int nC = in_sizes[6] / 128;
    const int N  = nA + nB + nC;
    const int E  = in_sizes[11];

    float* sup = nullptr;
    cudaGetSymbolAddress((void**)&sup, g_support);
    float* out = (float*)d_out;

    const int SMEM = 82944;
    cudaFuncSetAttribute(fused_enc_gcn<512>,
                         cudaFuncAttributeMaxDynamicSharedMemorySize, SMEM);
    cudaFuncSetAttribute(fused_enc_gcn<256>,
                         cudaFuncAttributeMaxDynamicSharedMemorySize, SMEM);
    cudaFuncSetAttribute(fused_enc_gcn<128>,
                         cudaFuncAttributeMaxDynamicSharedMemorySize, SMEM);

    // zero the accumulator (d_out is poisoned)
    {
        int n4 = N * 16;
        zero_kernel<<<(n4 + 255) / 256, 256>>>((float4*)out, n4);
    }

    // fused encoder + GCN -> g_support (BM=128 per block)
    fused_enc_gcn<512><<<(nA + 127) / 128, 128, SMEM>>>(
        feat_a, W_a, b_a, gcn_W, gcn_b, sup, nA);
    fused_enc_gcn<256><<<(nB + 127) / 128, 128, SMEM>>>(
        feat_b, W_b, b_b, gcn_W, gcn_b, sup + (size_t)nA * 64, nB);
    fused_enc_gcn<128><<<(nC + 127) / 128, 128, SMEM>>>(
        feat_c, W_c, b_c, gcn_W, gcn_b, sup + (size_t)(nA + nB) * 64, nC);

    // edge gather/scale/scatter-add into out
    {
        long long tot = (long long)E * 16;
        int blocks = (int)((tot + 255) / 256);
        edge_kernel<<<blocks, 256>>>(sup, edge_src, edge_dst, edge_w, out, E);
    }

    // row-wise L2 normalize in place
    normalize_kernel<<<(N + 7) / 8, 256>>>(out, N);
}

// round 17
// speedup vs baseline: 1.0550x; 1.0550x over previous
#include <cuda_runtime.h>
#include <cstdint>
#include <cstddef>

// ---------------------------------------------------------------------------
// NSHE fused: per-type encoder GEMM (relu(feat@W+b)) FUSED with GCN linear
// (@gcn_W + gcn_b) in one kernel -> g_support. Then edge gather*w scatter-add
// (L2 vector atomics) -> row L2-normalize.
// GEMM stage-1: tf32 mma.sync m16n8k8 with RAW fp32 fragments (HW truncates
// to tf32 - CUTLASS fast-tf32 style), 2-stage cp.async pipeline, BM=128,
// 128 threads, 3 CTAs/SM target (smem 55 KB, reg cap 166).
// GEMM stage-2: block-local 128x64 @ 64x64 from smem (RNA-rounded tf32).
// ---------------------------------------------------------------------------

#define NMAX 200000

__device__ float g_support[(size_t)NMAX * 64];

// ---- helpers --------------------------------------------------------------
__device__ __forceinline__ unsigned tf32u(float x) {
    unsigned u;
    asm("cvt.rna.tf32.f32 %0, %1;" : "=r"(u) : "f"(x));
    return u;
}
__device__ __forceinline__ float tf32f(float x) {
    return __uint_as_float(tf32u(x));
}

__device__ __forceinline__ void mma_tf32(float* c, const unsigned* a,
                                         const unsigned* b) {
    asm volatile(
        "mma.sync.aligned.m16n8k8.row.col.f32.tf32.tf32.f32 "
        "{%0,%1,%2,%3}, {%4,%5,%6,%7}, {%8,%9}, {%0,%1,%2,%3};"
        : "+f"(c[0]), "+f"(c[1]), "+f"(c[2]), "+f"(c[3])
        : "r"(a[0]), "r"(a[1]), "r"(a[2]), "r"(a[3]), "r"(b[0]), "r"(b[1]));
}

__device__ __forceinline__ void cp16(uint32_t dst, const void* src, bool p) {
    int sz = p ? 16 : 0;
    asm volatile("cp.async.cg.shared.global [%0], [%1], 16, %2;"
                 :: "r"(dst), "l"(src), "r"(sz));
}

// ---------------------------------------------------------------------------
// Dynamic smem (floats), total 13824 floats = 55296 B  ->  3 CTAs/SM:
//   stage 1: sA[2][128][36]  (2*4608 = 9216)   raw fp32 via cp.async
//            sB[2][32][72]   (2*2304 = 4608)   at offset 9216
//   stage 2 (aliased): sE[128][68] (8704, fits sA region)
//                      sW2[64][72] (4608, at offset 9216)
// Pipeline: prefetch (it+2) AFTER the trailing sync of iter it, into the
// buffer just consumed ((it)&1). One group in flight during compute.
// ---------------------------------------------------------------------------
template <int K>
__global__ void __launch_bounds__(128, 3)
fused_enc_gcn(const float* __restrict__ A, const float* __restrict__ W1,
              const float* __restrict__ b1, const float* __restrict__ gW,
              const float* __restrict__ gb, float* __restrict__ out, int nRows)
{
    extern __shared__ float smem[];
    float* sA = smem;             // 2 buffers, stride 4608 floats
    float* sB = smem + 9216;      // 2 buffers, stride 2304 floats

    const int t    = threadIdx.x;          // 0..127
    const int warp = t >> 5;                // 0..3
    const int lane = t & 31;
    const int row0 = blockIdx.x * 128;
    const int wrow = warp * 32;
    const int g4   = lane >> 2;             // 0..7
    const int t4   = lane & 3;              // 0..3

    const uint32_t sA_u = (uint32_t)__cvta_generic_to_shared(sA);
    const uint32_t sB_u = sA_u + 9216u * 4u;

    float acc[2][8][4];
#pragma unroll
    for (int mt = 0; mt < 2; mt++)
#pragma unroll
        for (int nt = 0; nt < 8; nt++)
#pragma unroll
            for (int i = 0; i < 4; i++) acc[mt][nt][i] = 0.f;

    auto load_tiles = [&](int buf, int k0) {
        // A tile: 128 rows x 32 k = 1024 float4, 8 per thread
#pragma unroll
        for (int i = 0; i < 8; i++) {
            int idx = t + i * 128;
            int r   = idx >> 3;        // 0..127
            int f   = idx & 7;         // 0..7
            int gr  = row0 + r;
            bool ok = gr < nRows;
            const float* src = A + (size_t)(ok ? gr : 0) * K + k0 + f * 4;
            cp16(sA_u + (uint32_t)(buf * 4608 + r * 36 + f * 4) * 4, src, ok);
        }
        // B tile: 32 x 64 = 512 float4, 4 per thread
#pragma unroll
        for (int i = 0; i < 4; i++) {
            int idx = t + i * 128;
            int kk  = idx >> 4;        // 0..31
            int f   = idx & 15;        // 0..15
            cp16(sB_u + (uint32_t)(buf * 2304 + kk * 72 + f * 4) * 4,
                 W1 + (size_t)(k0 + kk) * 64 + f * 4, true);
        }
        asm volatile("cp.async.commit_group;");
    };

    constexpr int NIT = K / 32;
    load_tiles(0, 0);
    if (NIT > 1) load_tiles(1, 32);

    for (int it = 0; it < NIT; ++it) {
        // wait for buffer (it & 1): one newer group may stay in flight
        if (it + 1 < NIT)
            asm volatile("cp.async.wait_group 1;");
        else
            asm volatile("cp.async.wait_group 0;");
        __syncthreads();

        const float* bA = sA + (it & 1) * 4608;
        const float* bB = sB + (it & 1) * 2304;
#pragma unroll
        for (int k8 = 0; k8 < 4; k8++) {
            unsigned bf[8][2];
#pragma unroll
            for (int nt = 0; nt < 8; nt++) {
                bf[nt][0] = __float_as_uint(bB[(k8 * 8 + t4    ) * 72 + nt * 8 + g4]);
                bf[nt][1] = __float_as_uint(bB[(k8 * 8 + t4 + 4) * 72 + nt * 8 + g4]);
            }
#pragma unroll
            for (int mt = 0; mt < 2; mt++) {
                int r = wrow + mt * 16 + g4;
                unsigned af[4];
                af[0] = __float_as_uint(bA[(r    ) * 36 + k8 * 8 + t4    ]);
                af[1] = __float_as_uint(bA[(r + 8) * 36 + k8 * 8 + t4    ]);
                af[2] = __float_as_uint(bA[(r    ) * 36 + k8 * 8 + t4 + 4]);
                af[3] = __float_as_uint(bA[(r + 8) * 36 + k8 * 8 + t4 + 4]);
#pragma unroll
                for (int nt = 0; nt < 8; nt++)
                    mma_tf32(acc[mt][nt], af, bf[nt]);
            }
        }
        __syncthreads();   // all warps done with buffer (it & 1)
        if (it + 2 < NIT) load_tiles(it & 1, (it + 2) * 32);
    }
    __syncthreads();   // smem about to be re-purposed

    // ---- stage 2 setup: relu(acc+b1) -> sE (RNA tf32), gcn_W -> sW2 ----
    float* sE  = smem;          // [128][68]
    float* sW2 = smem + 9216;   // [64][72]

#pragma unroll
    for (int nt = 0; nt < 8; nt++) {
        int col   = nt * 8 + 2 * t4;
        float bb0 = b1[col];
        float bb1 = b1[col + 1];
#pragma unroll
        for (int mt = 0; mt < 2; mt++)
#pragma unroll
            for (int h = 0; h < 2; h++) {
                int r = wrow + mt * 16 + h * 8 + g4;
                float x0 = fmaxf(acc[mt][nt][h * 2 + 0] + bb0, 0.f);
                float x1 = fmaxf(acc[mt][nt][h * 2 + 1] + bb1, 0.f);
                *reinterpret_cast<float2*>(&sE[r * 68 + col]) =
                    make_float2(tf32f(x0), tf32f(x1));
            }
    }
#pragma unroll
    for (int i = 0; i < 8; i++) {
        int idx = t + i * 128;   // 0..1023
        int kk  = idx >> 4;
        int f   = idx & 15;
        float4 v = *reinterpret_cast<const float4*>(gW + (size_t)kk * 64 + f * 4);
        sW2[kk * 72 + f * 4 + 0] = tf32f(v.x);
        sW2[kk * 72 + f * 4 + 1] = tf32f(v.y);
        sW2[kk * 72 + f * 4 + 2] = tf32f(v.z);
        sW2[kk * 72 + f * 4 + 3] = tf32f(v.w);
    }
    __syncthreads();

    // ---- stage 2 MMA: 128x64 @ 64x64 (reuse acc registers) ----
#pragma unroll
    for (int mt = 0; mt < 2; mt++)
#pragma unroll
        for (int nt = 0; nt < 8; nt++)
#pragma unroll
            for (int i = 0; i < 4; i++) acc[mt][nt][i] = 0.f;

#pragma unroll
    for (int k8 = 0; k8 < 8; k8++) {
        unsigned bf[8][2];
#pragma unroll
        for (int nt = 0; nt < 8; nt++) {
            bf[nt][0] = __float_as_uint(sW2[(k8 * 8 + t4    ) * 72 + nt * 8 + g4]);
            bf[nt][1] = __float_as_uint(sW2[(k8 * 8 + t4 + 4) * 72 + nt * 8 + g4]);
        }
#pragma unroll
        for (int mt = 0; mt < 2; mt++) {
            int r = wrow + mt * 16 + g4;
            unsigned af[4];
            af[0] = __float_as_uint(sE[(r    ) * 68 + k8 * 8 + t4    ]);
            af[1] = __float_as_uint(sE[(r + 8) * 68 + k8 * 8 + t4    ]);
            af[2] = __float_as_uint(sE[(r    ) * 68 + k8 * 8 + t4 + 4]);
            af[3] = __float_as_uint(sE[(r + 8) * 68 + k8 * 8 + t4 + 4]);
#pragma unroll
            for (int nt = 0; nt < 8; nt++)
                mma_tf32(acc[mt][nt], af, bf[nt]);
        }
    }

    // ---- epilogue: + gcn_b, store support ----
#pragma unroll
    for (int nt = 0; nt < 8; nt++) {
        int col   = nt * 8 + 2 * t4;
        float bb0 = gb[col];
        float bb1 = gb[col + 1];
#pragma unroll
        for (int mt = 0; mt < 2; mt++)
#pragma unroll
            for (int h = 0; h < 2; h++) {
                int gr = row0 + wrow + mt * 16 + h * 8 + g4;
                if (gr < nRows) {
                    *reinterpret_cast<float2*>(out + (size_t)gr * 64 + col) =
                        make_float2(acc[mt][nt][h * 2 + 0] + bb0,
                                    acc[mt][nt][h * 2 + 1] + bb1);
                }
            }
    }
}

// ---------------------------------------------------------------------------
// Edge scatter: out[dst] += support[src] * w, 16 threads/edge (float4 each).
// support (51 MB) + out (51 MB) are L2-resident; v4 red cuts atomic op count.
// ---------------------------------------------------------------------------
__global__ void __launch_bounds__(256)
edge_kernel(const float* __restrict__ support, const int* __restrict__ src,
            const int* __restrict__ dst, const float* __restrict__ w,
            float* __restrict__ out, int E)
{
    int g   = blockIdx.x * 256 + threadIdx.x;
    int e   = g >> 4;
    int sub = g & 15;
    if (e >= E) return;
    int   s  = src[e];
    int   d  = dst[e];
    float wt = w[e];
    float4 v = *reinterpret_cast<const float4*>(support + (size_t)s * 64 + sub * 4);
    float* o = out + (size_t)d * 64 + sub * 4;
    asm volatile("red.global.add.v4.f32 [%0], {%1, %2, %3, %4};"
                 :: "l"(o), "f"(v.x * wt), "f"(v.y * wt),
                    "f"(v.z * wt), "f"(v.w * wt)
                 : "memory");
}

// ---------------------------------------------------------------------------
__global__ void __launch_bounds__(256)
zero_kernel(float4* __restrict__ out, int n4)
{
    int i = blockIdx.x * 256 + threadIdx.x;
    if (i < n4) out[i] = make_float4(0.f, 0.f, 0.f, 0.f);
}

__global__ void __launch_bounds__(256)
normalize_kernel(float* __restrict__ out, int N)
{
    int row  = blockIdx.x * 8 + (threadIdx.x >> 5);
    int lane = threadIdx.x & 31;
    if (row >= N) return;
    float* p = out + (size_t)row * 64;
    float2 v = *reinterpret_cast<float2*>(p + lane * 2);
    float ss = v.x * v.x + v.y * v.y;
#pragma unroll
    for (int o = 16; o > 0; o >>= 1) ss += __shfl_xor_sync(0xFFFFFFFFu, ss, o);
    float inv = 1.0f / fmaxf(sqrtf(ss), 1e-12f);
    v.x *= inv;
    v.y *= inv;
    *reinterpret_cast<float2*>(p + lane * 2) = v;
}

// ---------------------------------------------------------------------------
extern "C" void kernel_launch(void* const* d_in, const int* in_sizes, int n_in,
                              void* d_out, int out_size)
{
    const float* feat_a   = (const float*)d_in[0];
    const float* W_a      = (const float*)d_in[1];
    const float* b_a      = (const float*)d_in[2];
    const float* feat_b   = (const float*)d_in[3];
    const float* W_b      = (const float*)d_in[4];
    const float* b_b      = (const float*)d_in[5];
    const float* feat_c   = (const float*)d_in[6];
    const float* W_c      = (const float*)d_in[7];
    const float* b_c      = (const float*)d_in[8];
    const float* gcn_W    = (const float*)d_in[9];
    const float* gcn_b    = (const float*)d_in[10];
    const float* edge_w   = (const float*)d_in[11];
    const int*   edge_src = (const int*)d_in[12];
    const int*   edge_dst = (const int*)d_in[13];

    const int nA = in_sizes[0] / 512;
    const int nB = in_sizes[3] / 256;
    const int nC = in_sizes[6] / 128;
    const int N  = nA + nB + nC;
    const int E  = in_sizes[11];

    float* sup = nullptr;
    cudaGetSymbolAddress((void**)&sup, g_support);
    float* out = (float*)d_out;

    const int SMEM = 55296;
    cudaFuncSetAttribute(fused_enc_gcn<512>,
                         cudaFuncAttributeMaxDynamicSharedMemorySize, SMEM);
    cudaFuncSetAttribute(fused_enc_gcn<256>,
                         cudaFuncAttributeMaxDynamicSharedMemorySize, SMEM);
    cudaFuncSetAttribute(fused_enc_gcn<128>,
                         cudaFuncAttributeMaxDynamicSharedMemorySize, SMEM);

    // zero the accumulator (d_out is poisoned)
    {
        int n4 = N * 16;
        zero_kernel<<<(n4 + 255) / 256, 256>>>((float4*)out, n4);
    }

    // fused encoder + GCN -> g_support (BM=128 per block)
    fused_enc_gcn<512><<<(nA + 127) / 128, 128, SMEM>>>(
        feat_a, W_a, b_a, gcn_W, gcn_b, sup, nA);
    fused_enc_gcn<256><<<(nB + 127) / 128, 128, SMEM>>>(
        feat_b, W_b, b_b, gcn_W, gcn_b, sup + (size_t)nA * 64, nB);
    fused_enc_gcn<128><<<(nC + 127) / 128, 128, SMEM>>>(
        feat_c, W_c, b_c, gcn_W, gcn_b, sup + (size_t)(nA + nB) * 64, nC);

    // edge gather/scale/scatter-add into out
    {
        long long tot = (long long)E * 16;
        int blocks = (int)((tot + 255) / 256);
        edge_kernel<<<blocks, 256>>>(sup, edge_src, edge_dst, edge_w, out, E);
    }

    // row-wise L2 normalize in place
    normalize_kernel<<<(N + 7) / 8, 256>>>(out, N);
}